// round 16
// baseline (speedup 1.0000x reference)
#include <cuda_runtime.h>
#include <cuda_fp16.h>
#include <cstdint>

#define NN 4096
#define DD 1024
#define EE 65536
#define NB 26
#define WELEMS (1024*1024)

// ---------------- device scratch (no runtime alloc) -------------------------
__device__ __half  g_Wh[2][(size_t)NB * WELEMS];  // transposed fp16 weights: [bin][n][k]
__device__ __half  g_Ah[(size_t)NN * DD];         // GEMM A operand fp16
__device__ __half  g_Zh[(size_t)NB * NN * DD];    // Z[bin][node][col] fp16
__device__ int     g_cnt[NN];
__device__ int     g_fill[NN];
__device__ int     g_rowptr[NN + 1];
__device__ int     g_et[EE];
__device__ int     g_ewi[EE];
__device__ float4  g_ebas[EE];

// ---------------- helpers ----------------------------------------------------
__device__ __forceinline__ uint32_t smem_u32(const void* p) {
    uint32_t a;
    asm("{ .reg .u64 t; cvta.to.shared.u64 t, %1; cvt.u32.u64 %0, t; }" : "=r"(a) : "l"(p));
    return a;
}
#define CP_ASYNC16(dst_u32, src) \
    asm volatile("cp.async.cg.shared.global [%0], [%1], 16;" :: "r"(dst_u32), "l"(src))
#define CP_COMMIT() asm volatile("cp.async.commit_group;")
#define CP_WAIT(n)  asm volatile("cp.async.wait_group %0;" :: "n"(n))

#define LDSM4(r, addr) \
    asm volatile("ldmatrix.sync.aligned.m8n8.x4.shared.b16 {%0,%1,%2,%3}, [%4];" \
        : "=r"((r)[0]), "=r"((r)[1]), "=r"((r)[2]), "=r"((r)[3]) : "r"(addr))

// ---------------- conversion / prep kernels -----------------------------------
__global__ void cvt_a(const float* __restrict__ x) {
    const size_t i = ((size_t)blockIdx.x * 256 + threadIdx.x) * 4;
    float4 v = *(const float4*)(x + i);
    __half2 h0 = __floats2half2_rn(v.x, v.y);
    __half2 h1 = __floats2half2_rn(v.z, v.w);
    uint2 o;
    o.x = *(uint32_t*)&h0; o.y = *(uint32_t*)&h1;
    *(uint2*)(&g_Ah[i]) = o;
}

// transpose + fp16 for BOTH layers, half2-wide stores:
// g_Wh[l][bin][n][k] = W[l][bin][k][n]; bin 25 = root.
__global__ void cvt_w_t(const float* __restrict__ W1, const float* __restrict__ root1,
                        const float* __restrict__ W2, const float* __restrict__ root2) {
    __shared__ float tile[64][33];
    const int bz = blockIdx.z;              // 0..51
    const int layer = bz >= 26;
    const int bin = layer ? bz - 26 : bz;
    const float* W    = layer ? W2 : W1;
    const float* root = layer ? root2 : root1;
    const float* src = (bin < 25) ? (W + (size_t)bin * WELEMS) : root;
    const int n0 = blockIdx.x * 32;
    const int k0 = blockIdx.y * 64;
    const int tx = threadIdx.x, ty = threadIdx.y;   // 32 x 8
    #pragma unroll
    for (int r = ty; r < 64; r += 8)
        tile[r][tx] = src[(size_t)(k0 + r) * DD + n0 + tx];
    __syncthreads();
    __half* dst = g_Wh[layer] + (size_t)bin * WELEMS;
    #pragma unroll
    for (int r = ty; r < 32; r += 8) {
        __half2 h = __floats2half2_rn(tile[2 * tx][r], tile[2 * tx + 1][r]);
        *(__half2*)(dst + (size_t)(n0 + r) * DD + k0 + 2 * tx) = h;
    }
}

__global__ void hist(const int* __restrict__ heads) {
    int e = blockIdx.x * 256 + threadIdx.x;
    atomicAdd(&g_cnt[heads[e]], 1);
}

__global__ void scan_rowptr() {
    __shared__ int part[1024];
    const int tid = threadIdx.x;
    int4 c = *(const int4*)&g_cnt[tid * 4];
    int s4 = c.x + c.y + c.z + c.w;
    part[tid] = s4;
    __syncthreads();
    for (int off = 1; off < 1024; off <<= 1) {
        int v = (tid >= off) ? part[tid - off] : 0;
        __syncthreads();
        part[tid] += v;
        __syncthreads();
    }
    int excl = part[tid] - s4;
    g_rowptr[tid * 4 + 0] = excl;
    g_rowptr[tid * 4 + 1] = excl + c.x;
    g_rowptr[tid * 4 + 2] = excl + c.x + c.y;
    g_rowptr[tid * 4 + 3] = excl + c.x + c.y + c.z;
    if (tid == 1023) g_rowptr[4096] = excl + s4;
}

__global__ void build_edges(const float* __restrict__ pts,
                            const int* __restrict__ tails,
                            const int* __restrict__ heads) {
    const int e = blockIdx.x * 256 + threadIdx.x;
    const int t = tails[e], h = heads[e];
    const float dx = __ldg(pts + 2 * t)     - __ldg(pts + 2 * h);
    const float dy = __ldg(pts + 2 * t + 1) - __ldg(pts + 2 * h + 1);
    const float px = fminf(fmaxf(dx * (0.5f / 256.0f) + 0.5f, 0.f), 1.f);
    const float py = fminf(fmaxf(dy * (0.5f / 256.0f) + 0.5f, 0.f), 1.f);
    const float vx = px * 4.f, vy = py * 4.f;
    const float fx = fminf(floorf(vx), 3.f), fy = fminf(floorf(vy), 3.f);
    const float rx = vx - fx, ry = vy - fy;
    const int wi = (int)fx + 5 * (int)fy;
    float4 b;
    b.x = (1.f - rx) * (1.f - ry);
    b.y = rx * (1.f - ry);
    b.z = (1.f - rx) * ry;
    b.w = rx * ry;
    const int pos = g_rowptr[h] + atomicAdd(&g_fill[h], 1);
    g_et[pos] = t; g_ewi[pos] = wi; g_ebas[pos] = b;
}

// ---------------- fp16 GEMM: Z[bz] = A(4096x1024) @ Wt[bz]^T ------------------
// CTA 128x128, BK=32, 8 warps (2x4), warp tile 64x32, mma m16n8k16.f16.f32
// 3-stage cp.async; B fragments for BOTH kp halves prefetched up-front.
#define LDK 40                       // halves per smem row (80B stride, LDSM conflict-free)
#define ROWB (LDK * 2)               // 80 bytes
#define TILE_B (128 * ROWB)          // 10240 bytes per operand tile
#define BUF_B  (2 * TILE_B)          // 20480 bytes per stage
#define NSTAGE 3
#define SMEM_TOTAL (NSTAGE * BUF_B)  // 61440 bytes
#define NKT 32

extern __shared__ __align__(16) unsigned char dsm[];

__global__ __launch_bounds__(256, 2) void gemm_fp16(int layer) {
    const int tid  = threadIdx.x;
    const int lane = tid & 31;
    const int wid  = tid >> 5;
    const int wm0  = (wid >> 2) * 64;
    const int wn0  = (wid & 3) * 32;
    const int n0   = blockIdx.x << 7;
    const int m0   = blockIdx.y << 7;
    const int bz   = blockIdx.z;

    const __half* __restrict__ Ag = g_Ah + (size_t)m0 * DD;
    const __half* __restrict__ Bg = g_Wh[layer] + (size_t)bz * WELEMS + (size_t)n0 * DD;

    const uint32_t smem_base = smem_u32(dsm);

    // staging map: row=tid>>2 (0..63, +64 via d_off1), chunk=tid&3 (16B chunks)
    const int row0 = tid >> 2, ch = tid & 3;
    const __half* a_src0 = Ag + (size_t)row0 * DD + ch * 8;
    const __half* a_src1 = a_src0 + (size_t)64 * DD;
    const __half* b_src0 = Bg + (size_t)row0 * DD + ch * 8;
    const __half* b_src1 = b_src0 + (size_t)64 * DD;
    const uint32_t d_off0 = (uint32_t)row0 * ROWB + ch * 16;
    const uint32_t d_off1 = d_off0 + 64 * ROWB;

    #define STAGE(p, kt) do {                                                   \
        const uint32_t b_ = smem_base + (p) * BUF_B;                             \
        const int ko_ = (kt) * 32;                                               \
        CP_ASYNC16(b_ + d_off0,          a_src0 + ko_);                          \
        CP_ASYNC16(b_ + d_off1,          a_src1 + ko_);                          \
        CP_ASYNC16(b_ + TILE_B + d_off0, b_src0 + ko_);                          \
        CP_ASYNC16(b_ + TILE_B + d_off1, b_src1 + ko_);                          \
        CP_COMMIT();                                                             \
    } while (0)

    STAGE(0, 0);
    STAGE(1, 1);

    float acc[4][4][4];
    #pragma unroll
    for (int mi = 0; mi < 4; ++mi)
        #pragma unroll
        for (int ni = 0; ni < 4; ++ni)
            #pragma unroll
            for (int i = 0; i < 4; ++i) acc[mi][ni][i] = 0.f;

    // ldmatrix per-lane row/col mapping (proven R5 scheme)
    const int lane7  = lane & 7;
    const int arow_l = wm0 + ((lane & 8)  ? 8 : 0) + lane7;
    const int acol_l = (lane & 16) ? 8 : 0;
    const int brow_l = wn0 + ((lane & 16) ? 8 : 0) + lane7;
    const int bcol_l = (lane & 8)  ? 8 : 0;

    for (int kt = 0; kt < NKT; ++kt) {
        if (kt < NKT - 1) { CP_WAIT(1); } else { CP_WAIT(0); }
        __syncthreads();

        const uint32_t sA32 = smem_base + (kt % 3) * BUF_B;
        const uint32_t sB32 = sA32 + TILE_B;
        const uint32_t aab = sA32 + (uint32_t)(arow_l * LDK + acol_l) * 2;
        const uint32_t bab = sB32 + (uint32_t)(brow_l * LDK + bcol_l) * 2;

        // B fragments for BOTH kp halves + A kp0 loaded first
        uint32_t bf0[2][4], bf1[2][4], af[4][4];
        #pragma unroll
        for (int n2 = 0; n2 < 2; ++n2)
            LDSM4(bf0[n2], bab + (uint32_t)(n2 * 16 * LDK) * 2);
        #pragma unroll
        for (int n2 = 0; n2 < 2; ++n2)
            LDSM4(bf1[n2], bab + (uint32_t)(n2 * 16 * LDK + 16) * 2);
        #pragma unroll
        for (int mi = 0; mi < 4; ++mi)
            LDSM4(af[mi], aab + (uint32_t)(mi * 16 * LDK) * 2);

        // async stage issue hides under kp0 HMMAs
        if (kt < NKT - 2) STAGE((kt + 2) % 3, kt + 2);

        #pragma unroll
        for (int mi = 0; mi < 4; ++mi)
            #pragma unroll
            for (int ni = 0; ni < 4; ++ni) {
                float* c = acc[mi][ni];
                asm volatile(
                    "mma.sync.aligned.m16n8k16.row.col.f32.f16.f16.f32 "
                    "{%0,%1,%2,%3}, {%4,%5,%6,%7}, {%8,%9}, {%0,%1,%2,%3};\n"
                    : "+f"(c[0]), "+f"(c[1]), "+f"(c[2]), "+f"(c[3])
                    : "r"(af[mi][0]), "r"(af[mi][1]), "r"(af[mi][2]), "r"(af[mi][3]),
                      "r"(bf0[ni >> 1][(ni & 1) * 2]), "r"(bf0[ni >> 1][(ni & 1) * 2 + 1]));
            }

        // kp1: only A reloads (B already in registers)
        #pragma unroll
        for (int mi = 0; mi < 4; ++mi)
            LDSM4(af[mi], aab + (uint32_t)(mi * 16 * LDK + 16) * 2);
        #pragma unroll
        for (int mi = 0; mi < 4; ++mi)
            #pragma unroll
            for (int ni = 0; ni < 4; ++ni) {
                float* c = acc[mi][ni];
                asm volatile(
                    "mma.sync.aligned.m16n8k16.row.col.f32.f16.f16.f32 "
                    "{%0,%1,%2,%3}, {%4,%5,%6,%7}, {%8,%9}, {%0,%1,%2,%3};\n"
                    : "+f"(c[0]), "+f"(c[1]), "+f"(c[2]), "+f"(c[3])
                    : "r"(af[mi][0]), "r"(af[mi][1]), "r"(af[mi][2]), "r"(af[mi][3]),
                      "r"(bf1[ni >> 1][(ni & 1) * 2]), "r"(bf1[ni >> 1][(ni & 1) * 2 + 1]));
            }
    }
    #undef STAGE

    // epilogue: write fp16 Z (direct stores — proven fastest)
    const int ar = lane >> 2;
    const int ac = lane & 3;
    __half* Zb = g_Zh + ((size_t)bz * NN + m0) * DD + n0;
    #pragma unroll
    for (int mi = 0; mi < 4; ++mi) {
        #pragma unroll
        for (int ni = 0; ni < 4; ++ni) {
            const int r = wm0 + mi * 16 + ar;
            const int c = wn0 + ni * 8 + ac * 2;
            __half2 h01 = __floats2half2_rn(acc[mi][ni][0], acc[mi][ni][1]);
            __half2 h23 = __floats2half2_rn(acc[mi][ni][2], acc[mi][ni][3]);
            *(__half2*)(Zb + (size_t)r * DD + c)       = h01;
            *(__half2*)(Zb + (size_t)(r + 8) * DD + c) = h23;
        }
    }
}

// ---------------- per-head aggregation + fused epilogue ------------------------
__device__ __forceinline__ void h8_to_f(uint4 v, float* f) {
    float2 t;
    t = __half22float2(*(__half2*)&v.x); f[0] = t.x; f[1] = t.y;
    t = __half22float2(*(__half2*)&v.y); f[2] = t.x; f[3] = t.y;
    t = __half22float2(*(__half2*)&v.z); f[4] = t.x; f[5] = t.y;
    t = __half22float2(*(__half2*)&v.w); f[6] = t.x; f[7] = t.y;
}

__device__ __forceinline__ void edge_max(const uint4* r, const float4 b, float* m) {
    float z0[8], z1[8], z2[8], z3[8];
    h8_to_f(r[0], z0); h8_to_f(r[1], z1); h8_to_f(r[2], z2); h8_to_f(r[3], z3);
    #pragma unroll
    for (int i = 0; i < 8; ++i)
        m[i] = fmaxf(m[i], b.x * z0[i] + b.y * z1[i] + b.z * z2[i] + b.w * z3[i]);
}

__global__ void agg(int layer, const float* __restrict__ bias,
                    const float* __restrict__ descs, float* __restrict__ out) {
    const int h = blockIdx.x;
    const int tid = threadIdx.x;          // 128 threads, 8 cols each
    const int c = tid * 8;
    const int beg = g_rowptr[h], end = g_rowptr[h + 1];
    const size_t NND = (size_t)NN * DD;

    float m[8];
    #pragma unroll
    for (int i = 0; i < 8; ++i) m[i] = -3.4e38f;

    int e = beg;
    // unroll-by-4: 16 independent Z-row loads in flight per iteration
    for (; e + 4 <= end; e += 4) {
        uint4 r[4][4];
        float4 bb[4];
        #pragma unroll
        for (int j = 0; j < 4; ++j) {
            const int t  = __ldg(&g_et[e + j]);
            const int wi = __ldg(&g_ewi[e + j]);
            bb[j] = __ldg(&g_ebas[e + j]);
            const __half* z = g_Zh + ((size_t)wi * NN + t) * DD + c;
            r[j][0] = __ldg((const uint4*)(z));
            r[j][1] = __ldg((const uint4*)(z + NND));
            r[j][2] = __ldg((const uint4*)(z + 5 * NND));
            r[j][3] = __ldg((const uint4*)(z + 6 * NND));
        }
        #pragma unroll
        for (int j = 0; j < 4; ++j) edge_max(r[j], bb[j], m);
    }
    for (; e < end; ++e) {
        const int t  = __ldg(&g_et[e]);
        const int wi = __ldg(&g_ewi[e]);
        const float4 b = __ldg(&g_ebas[e]);
        const __half* z = g_Zh + ((size_t)wi * NN + t) * DD + c;
        uint4 r[4];
        r[0] = __ldg((const uint4*)(z));
        r[1] = __ldg((const uint4*)(z + NND));
        r[2] = __ldg((const uint4*)(z + 5 * NND));
        r[3] = __ldg((const uint4*)(z + 6 * NND));
        edge_max(r, b, m);
    }
    if (beg == end)
        #pragma unroll
        for (int i = 0; i < 8; ++i) m[i] = 0.f;

    float zr[8];
    h8_to_f(__ldg((const uint4*)(g_Zh + ((size_t)25 * NN + h) * DD + c)), zr);
    const float4 bi0 = __ldg((const float4*)(bias + c));
    const float4 bi1 = __ldg((const float4*)(bias + c + 4));
    float res[8];
    res[0] = m[0] + zr[0] + bi0.x; res[1] = m[1] + zr[1] + bi0.y;
    res[2] = m[2] + zr[2] + bi0.z; res[3] = m[3] + zr[3] + bi0.w;
    res[4] = m[4] + zr[4] + bi1.x; res[5] = m[5] + zr[5] + bi1.y;
    res[6] = m[6] + zr[6] + bi1.z; res[7] = m[7] + zr[7] + bi1.w;

    const size_t o = (size_t)h * DD + c;
    if (layer == 0) {
        uint4 w;
        __half2 p0 = __floats2half2_rn(fmaxf(res[0], 0.f), fmaxf(res[1], 0.f));
        __half2 p1 = __floats2half2_rn(fmaxf(res[2], 0.f), fmaxf(res[3], 0.f));
        __half2 p2 = __floats2half2_rn(fmaxf(res[4], 0.f), fmaxf(res[5], 0.f));
        __half2 p3 = __floats2half2_rn(fmaxf(res[6], 0.f), fmaxf(res[7], 0.f));
        w.x = *(uint32_t*)&p0; w.y = *(uint32_t*)&p1;
        w.z = *(uint32_t*)&p2; w.w = *(uint32_t*)&p3;
        *(uint4*)(&g_Ah[o]) = w;
    } else {
        const float4 d0 = __ldg((const float4*)(descs + o));
        const float4 d1 = __ldg((const float4*)(descs + o + 4));
        float4 o0 = make_float4(d0.x + 0.1f * res[0], d0.y + 0.1f * res[1],
                                d0.z + 0.1f * res[2], d0.w + 0.1f * res[3]);
        float4 o1 = make_float4(d1.x + 0.1f * res[4], d1.y + 0.1f * res[5],
                                d1.z + 0.1f * res[6], d1.w + 0.1f * res[7]);
        *(float4*)(out + o)     = o0;
        *(float4*)(out + o + 4) = o1;
    }
}

// ---------------- launch ---------------------------------------------------------
extern "C" void kernel_launch(void* const* d_in, const int* in_sizes, int n_in,
                              void* d_out, int out_size) {
    const float* descs = (const float*)d_in[0];
    const float* pts   = (const float*)d_in[1];
    const float* W1    = (const float*)d_in[2];
    const float* root1 = (const float*)d_in[3];
    const float* bias1 = (const float*)d_in[4];
    const float* W2    = (const float*)d_in[5];
    const float* root2 = (const float*)d_in[6];
    const float* bias2 = (const float*)d_in[7];
    const int*   tails = (const int*)d_in[8];
    const int*   heads = (const int*)d_in[9];
    float* out = (float*)d_out;

    cudaFuncSetAttribute(gemm_fp16, cudaFuncAttributeMaxDynamicSharedMemorySize, SMEM_TOTAL);

    // zero g_cnt/g_fill via capturable async memsets
    void* cnt_ptr = nullptr;  cudaGetSymbolAddress(&cnt_ptr, g_cnt);
    void* fill_ptr = nullptr; cudaGetSymbolAddress(&fill_ptr, g_fill);
    cudaMemsetAsync(cnt_ptr, 0, NN * sizeof(int));
    cudaMemsetAsync(fill_ptr, 0, NN * sizeof(int));

    // ncu captures launch #4 -> keep gemm_fp16 there.
    cvt_a<<<4096, 256>>>(descs);                                           // 1
    cvt_w_t<<<dim3(32, 16, 52), dim3(32, 8)>>>(W1, root1, W2, root2);      // 2
    hist<<<256, 256>>>(heads);                                             // 3
    gemm_fp16<<<dim3(8, 32, 26), 256, SMEM_TOTAL>>>(0);                    // 4  <- profiled
    scan_rowptr<<<1, 1024>>>();                                            // 5
    build_edges<<<256, 256>>>(pts, tails, heads);                          // 6
    agg<<<4096, 128>>>(0, bias1, nullptr, nullptr);                        // 7
    gemm_fp16<<<dim3(8, 32, 26), 256, SMEM_TOTAL>>>(1);                    // 8
    agg<<<4096, 128>>>(1, bias2, descs, out);                              // 9
}

// round 17
// speedup vs baseline: 1.0380x; 1.0380x over previous
#include <cuda_runtime.h>
#include <cuda_fp16.h>
#include <cstdint>

#define NN 4096
#define DD 1024
#define EE 65536
#define NB 26
#define WELEMS (1024*1024)

// ---------------- device scratch (no runtime alloc) -------------------------
__device__ __half  g_Wh[2][(size_t)NB * WELEMS];  // transposed fp16 weights: [bin][n][k]
__device__ __half  g_Ah[(size_t)NN * DD];         // GEMM A operand fp16
__device__ __half  g_Zh[(size_t)NB * NN * DD];    // Z[bin][node][col] fp16
__device__ int     g_cnt[NN];
__device__ int     g_fill[NN];
__device__ int     g_rowptr[NN + 1];
__device__ int     g_et[EE];
__device__ int     g_ewi[EE];
__device__ float4  g_ebas[EE];

// ---------------- helpers ----------------------------------------------------
__device__ __forceinline__ uint32_t smem_u32(const void* p) {
    uint32_t a;
    asm("{ .reg .u64 t; cvta.to.shared.u64 t, %1; cvt.u32.u64 %0, t; }" : "=r"(a) : "l"(p));
    return a;
}
#define CP_ASYNC16(dst_u32, src) \
    asm volatile("cp.async.cg.shared.global [%0], [%1], 16;" :: "r"(dst_u32), "l"(src))
#define CP_COMMIT() asm volatile("cp.async.commit_group;")
#define CP_WAIT(n)  asm volatile("cp.async.wait_group %0;" :: "n"(n))

#define LDSM4(r, addr) \
    asm volatile("ldmatrix.sync.aligned.m8n8.x4.shared.b16 {%0,%1,%2,%3}, [%4];" \
        : "=r"((r)[0]), "=r"((r)[1]), "=r"((r)[2]), "=r"((r)[3]) : "r"(addr))

// ---------------- conversion / prep kernels -----------------------------------
__global__ void cvt_a(const float* __restrict__ x) {
    const size_t i = ((size_t)blockIdx.x * 256 + threadIdx.x) * 4;
    float4 v = *(const float4*)(x + i);
    __half2 h0 = __floats2half2_rn(v.x, v.y);
    __half2 h1 = __floats2half2_rn(v.z, v.w);
    uint2 o;
    o.x = *(uint32_t*)&h0; o.y = *(uint32_t*)&h1;
    *(uint2*)(&g_Ah[i]) = o;
}

// transpose + fp16 for BOTH layers, half2-wide stores:
// g_Wh[l][bin][n][k] = W[l][bin][k][n]; bin 25 = root.
__global__ void cvt_w_t(const float* __restrict__ W1, const float* __restrict__ root1,
                        const float* __restrict__ W2, const float* __restrict__ root2) {
    __shared__ float tile[64][33];
    const int bz = blockIdx.z;              // 0..51
    const int layer = bz >= 26;
    const int bin = layer ? bz - 26 : bz;
    const float* W    = layer ? W2 : W1;
    const float* root = layer ? root2 : root1;
    const float* src = (bin < 25) ? (W + (size_t)bin * WELEMS) : root;
    const int n0 = blockIdx.x * 32;
    const int k0 = blockIdx.y * 64;
    const int tx = threadIdx.x, ty = threadIdx.y;   // 32 x 8
    #pragma unroll
    for (int r = ty; r < 64; r += 8)
        tile[r][tx] = src[(size_t)(k0 + r) * DD + n0 + tx];
    __syncthreads();
    __half* dst = g_Wh[layer] + (size_t)bin * WELEMS;
    #pragma unroll
    for (int r = ty; r < 32; r += 8) {
        __half2 h = __floats2half2_rn(tile[2 * tx][r], tile[2 * tx + 1][r]);
        *(__half2*)(dst + (size_t)(n0 + r) * DD + k0 + 2 * tx) = h;
    }
}

__global__ void hist(const int* __restrict__ heads) {
    int e = blockIdx.x * 256 + threadIdx.x;
    atomicAdd(&g_cnt[heads[e]], 1);
}

__global__ void scan_rowptr() {
    __shared__ int part[1024];
    const int tid = threadIdx.x;
    int4 c = *(const int4*)&g_cnt[tid * 4];
    int s4 = c.x + c.y + c.z + c.w;
    part[tid] = s4;
    __syncthreads();
    for (int off = 1; off < 1024; off <<= 1) {
        int v = (tid >= off) ? part[tid - off] : 0;
        __syncthreads();
        part[tid] += v;
        __syncthreads();
    }
    int excl = part[tid] - s4;
    g_rowptr[tid * 4 + 0] = excl;
    g_rowptr[tid * 4 + 1] = excl + c.x;
    g_rowptr[tid * 4 + 2] = excl + c.x + c.y;
    g_rowptr[tid * 4 + 3] = excl + c.x + c.y + c.z;
    if (tid == 1023) g_rowptr[4096] = excl + s4;
}

__global__ void build_edges(const float* __restrict__ pts,
                            const int* __restrict__ tails,
                            const int* __restrict__ heads) {
    const int e = blockIdx.x * 256 + threadIdx.x;
    const int t = tails[e], h = heads[e];
    const float dx = __ldg(pts + 2 * t)     - __ldg(pts + 2 * h);
    const float dy = __ldg(pts + 2 * t + 1) - __ldg(pts + 2 * h + 1);
    const float px = fminf(fmaxf(dx * (0.5f / 256.0f) + 0.5f, 0.f), 1.f);
    const float py = fminf(fmaxf(dy * (0.5f / 256.0f) + 0.5f, 0.f), 1.f);
    const float vx = px * 4.f, vy = py * 4.f;
    const float fx = fminf(floorf(vx), 3.f), fy = fminf(floorf(vy), 3.f);
    const float rx = vx - fx, ry = vy - fy;
    const int wi = (int)fx + 5 * (int)fy;
    float4 b;
    b.x = (1.f - rx) * (1.f - ry);
    b.y = rx * (1.f - ry);
    b.z = (1.f - rx) * ry;
    b.w = rx * ry;
    const int pos = g_rowptr[h] + atomicAdd(&g_fill[h], 1);
    g_et[pos] = t; g_ewi[pos] = wi; g_ebas[pos] = b;
}

// ---------------- fp16 GEMM: Z[bz] = A(4096x1024) @ Wt[bz]^T ------------------
// CTA 128x128, BK=32, 8 warps (2x4), warp tile 64x32, mma m16n8k16.f16.f32
// 3-stage cp.async; LDSM kp0 issued BEFORE cp.async stage (MIO ordering).
// EXACT R15 mainloop (proven 518us, regs 122, tensor 71%).
#define LDK 40                       // halves per smem row (80B stride, LDSM conflict-free)
#define ROWB (LDK * 2)               // 80 bytes
#define TILE_B (128 * ROWB)          // 10240 bytes per operand tile
#define BUF_B  (2 * TILE_B)          // 20480 bytes per stage
#define NSTAGE 3
#define SMEM_TOTAL (NSTAGE * BUF_B)  // 61440 bytes
#define NKT 32

extern __shared__ __align__(16) unsigned char dsm[];

__global__ __launch_bounds__(256, 2) void gemm_fp16(int layer) {
    const int tid  = threadIdx.x;
    const int lane = tid & 31;
    const int wid  = tid >> 5;
    const int wm0  = (wid >> 2) * 64;
    const int wn0  = (wid & 3) * 32;
    const int n0   = blockIdx.x << 7;
    const int m0   = blockIdx.y << 7;
    const int bz   = blockIdx.z;

    const __half* __restrict__ Ag = g_Ah + (size_t)m0 * DD;
    const __half* __restrict__ Bg = g_Wh[layer] + (size_t)bz * WELEMS + (size_t)n0 * DD;

    const uint32_t smem_base = smem_u32(dsm);

    // staging map: row=tid>>2 (0..63, +64 via d_off1), chunk=tid&3 (16B chunks)
    const int row0 = tid >> 2, ch = tid & 3;
    const __half* a_src0 = Ag + (size_t)row0 * DD + ch * 8;
    const __half* a_src1 = a_src0 + (size_t)64 * DD;
    const __half* b_src0 = Bg + (size_t)row0 * DD + ch * 8;
    const __half* b_src1 = b_src0 + (size_t)64 * DD;
    const uint32_t d_off0 = (uint32_t)row0 * ROWB + ch * 16;
    const uint32_t d_off1 = d_off0 + 64 * ROWB;

    #define STAGE(p, kt) do {                                                   \
        const uint32_t b_ = smem_base + (p) * BUF_B;                             \
        const int ko_ = (kt) * 32;                                               \
        CP_ASYNC16(b_ + d_off0,          a_src0 + ko_);                          \
        CP_ASYNC16(b_ + d_off1,          a_src1 + ko_);                          \
        CP_ASYNC16(b_ + TILE_B + d_off0, b_src0 + ko_);                          \
        CP_ASYNC16(b_ + TILE_B + d_off1, b_src1 + ko_);                          \
        CP_COMMIT();                                                             \
    } while (0)

    STAGE(0, 0);
    STAGE(1, 1);

    float acc[4][4][4];
    #pragma unroll
    for (int mi = 0; mi < 4; ++mi)
        #pragma unroll
        for (int ni = 0; ni < 4; ++ni)
            #pragma unroll
            for (int i = 0; i < 4; ++i) acc[mi][ni][i] = 0.f;

    // ldmatrix per-lane row/col mapping (proven R5 scheme)
    const int lane7  = lane & 7;
    const int arow_l = wm0 + ((lane & 8)  ? 8 : 0) + lane7;
    const int acol_l = (lane & 16) ? 8 : 0;
    const int brow_l = wn0 + ((lane & 16) ? 8 : 0) + lane7;
    const int bcol_l = (lane & 8)  ? 8 : 0;

    for (int kt = 0; kt < NKT; ++kt) {
        if (kt < NKT - 1) { CP_WAIT(1); } else { CP_WAIT(0); }
        __syncthreads();

        const uint32_t sA32 = smem_base + (kt % 3) * BUF_B;
        const uint32_t sB32 = sA32 + TILE_B;
        const uint32_t aab = sA32 + (uint32_t)(arow_l * LDK + acol_l) * 2;
        const uint32_t bab = sB32 + (uint32_t)(brow_l * LDK + bcol_l) * 2;

        // kp0 fragment loads FIRST (tensor pipe ramps immediately) ...
        uint32_t af[4][4], bf[2][4];
        #pragma unroll
        for (int n2 = 0; n2 < 2; ++n2)
            LDSM4(bf[n2], bab + (uint32_t)(n2 * 16 * LDK) * 2);
        #pragma unroll
        for (int mi = 0; mi < 4; ++mi)
            LDSM4(af[mi], aab + (uint32_t)(mi * 16 * LDK) * 2);

        // ... async stage issue hides under kp0 HMMAs
        if (kt < NKT - 2) STAGE((kt + 2) % 3, kt + 2);

        #pragma unroll
        for (int mi = 0; mi < 4; ++mi)
            #pragma unroll
            for (int ni = 0; ni < 4; ++ni) {
                float* c = acc[mi][ni];
                asm volatile(
                    "mma.sync.aligned.m16n8k16.row.col.f32.f16.f16.f32 "
                    "{%0,%1,%2,%3}, {%4,%5,%6,%7}, {%8,%9}, {%0,%1,%2,%3};\n"
                    : "+f"(c[0]), "+f"(c[1]), "+f"(c[2]), "+f"(c[3])
                    : "r"(af[mi][0]), "r"(af[mi][1]), "r"(af[mi][2]), "r"(af[mi][3]),
                      "r"(bf[ni >> 1][(ni & 1) * 2]), "r"(bf[ni >> 1][(ni & 1) * 2 + 1]));
            }

        // kp1
        #pragma unroll
        for (int n2 = 0; n2 < 2; ++n2)
            LDSM4(bf[n2], bab + (uint32_t)(n2 * 16 * LDK + 16) * 2);
        #pragma unroll
        for (int mi = 0; mi < 4; ++mi)
            LDSM4(af[mi], aab + (uint32_t)(mi * 16 * LDK + 16) * 2);
        #pragma unroll
        for (int mi = 0; mi < 4; ++mi)
            #pragma unroll
            for (int ni = 0; ni < 4; ++ni) {
                float* c = acc[mi][ni];
                asm volatile(
                    "mma.sync.aligned.m16n8k16.row.col.f32.f16.f16.f32 "
                    "{%0,%1,%2,%3}, {%4,%5,%6,%7}, {%8,%9}, {%0,%1,%2,%3};\n"
                    : "+f"(c[0]), "+f"(c[1]), "+f"(c[2]), "+f"(c[3])
                    : "r"(af[mi][0]), "r"(af[mi][1]), "r"(af[mi][2]), "r"(af[mi][3]),
                      "r"(bf[ni >> 1][(ni & 1) * 2]), "r"(bf[ni >> 1][(ni & 1) * 2 + 1]));
            }
    }
    #undef STAGE

    // epilogue: write fp16 Z (direct stores — proven fastest)
    const int ar = lane >> 2;
    const int ac = lane & 3;
    __half* Zb = g_Zh + ((size_t)bz * NN + m0) * DD + n0;
    #pragma unroll
    for (int mi = 0; mi < 4; ++mi) {
        #pragma unroll
        for (int ni = 0; ni < 4; ++ni) {
            const int r = wm0 + mi * 16 + ar;
            const int c = wn0 + ni * 8 + ac * 2;
            __half2 h01 = __floats2half2_rn(acc[mi][ni][0], acc[mi][ni][1]);
            __half2 h23 = __floats2half2_rn(acc[mi][ni][2], acc[mi][ni][3]);
            *(__half2*)(Zb + (size_t)r * DD + c)       = h01;
            *(__half2*)(Zb + (size_t)(r + 8) * DD + c) = h23;
        }
    }
}

// ---------------- per-head aggregation + fused epilogue ------------------------
__device__ __forceinline__ void h8_to_f(uint4 v, float* f) {
    float2 t;
    t = __half22float2(*(__half2*)&v.x); f[0] = t.x; f[1] = t.y;
    t = __half22float2(*(__half2*)&v.y); f[2] = t.x; f[3] = t.y;
    t = __half22float2(*(__half2*)&v.z); f[4] = t.x; f[5] = t.y;
    t = __half22float2(*(__half2*)&v.w); f[6] = t.x; f[7] = t.y;
}

// edge metadata staged through smem (one global load per edge, uniform LDS reads)
__global__ void agg(int layer, const float* __restrict__ bias,
                    const float* __restrict__ descs, float* __restrict__ out) {
    __shared__ int    s_t[128];
    __shared__ int    s_wi[128];
    __shared__ float4 s_b[128];

    const int h = blockIdx.x;
    const int tid = threadIdx.x;          // 128 threads, 8 cols each
    const int c = tid * 8;
    const int beg = g_rowptr[h], end = g_rowptr[h + 1];
    const size_t NND = (size_t)NN * DD;

    float m[8];
    #pragma unroll
    for (int i = 0; i < 8; ++i) m[i] = -3.4e38f;

    for (int cs = beg; cs < end; cs += 128) {
        const int n = min(128, end - cs);
        if (tid < n) {
            s_t[tid]  = g_et[cs + tid];
            s_wi[tid] = g_ewi[cs + tid];
            s_b[tid]  = g_ebas[cs + tid];
        }
        __syncthreads();

        int j = 0;
        for (; j + 2 <= n; j += 2) {
            const __half* za = g_Zh + ((size_t)s_wi[j]     * NN + s_t[j])     * DD + c;
            const __half* zb = g_Zh + ((size_t)s_wi[j + 1] * NN + s_t[j + 1]) * DD + c;
            const float4 b0 = s_b[j];
            const float4 b1 = s_b[j + 1];
            const uint4 ra0 = __ldg((const uint4*)(za));
            const uint4 ra1 = __ldg((const uint4*)(za + NND));
            const uint4 ra2 = __ldg((const uint4*)(za + 5 * NND));
            const uint4 ra3 = __ldg((const uint4*)(za + 6 * NND));
            const uint4 rb0 = __ldg((const uint4*)(zb));
            const uint4 rb1 = __ldg((const uint4*)(zb + NND));
            const uint4 rb2 = __ldg((const uint4*)(zb + 5 * NND));
            const uint4 rb3 = __ldg((const uint4*)(zb + 6 * NND));
            float z0[8], z1[8], z2[8], z3[8];
            h8_to_f(ra0, z0); h8_to_f(ra1, z1); h8_to_f(ra2, z2); h8_to_f(ra3, z3);
            #pragma unroll
            for (int i = 0; i < 8; ++i)
                m[i] = fmaxf(m[i], b0.x * z0[i] + b0.y * z1[i] + b0.z * z2[i] + b0.w * z3[i]);
            h8_to_f(rb0, z0); h8_to_f(rb1, z1); h8_to_f(rb2, z2); h8_to_f(rb3, z3);
            #pragma unroll
            for (int i = 0; i < 8; ++i)
                m[i] = fmaxf(m[i], b1.x * z0[i] + b1.y * z1[i] + b1.z * z2[i] + b1.w * z3[i]);
        }
        if (j < n) {
            const __half* za = g_Zh + ((size_t)s_wi[j] * NN + s_t[j]) * DD + c;
            const float4 b0 = s_b[j];
            float z0[8], z1[8], z2[8], z3[8];
            h8_to_f(__ldg((const uint4*)(za)),            z0);
            h8_to_f(__ldg((const uint4*)(za + NND)),      z1);
            h8_to_f(__ldg((const uint4*)(za + 5 * NND)),  z2);
            h8_to_f(__ldg((const uint4*)(za + 6 * NND)),  z3);
            #pragma unroll
            for (int i = 0; i < 8; ++i)
                m[i] = fmaxf(m[i], b0.x * z0[i] + b0.y * z1[i] + b0.z * z2[i] + b0.w * z3[i]);
        }
        __syncthreads();
    }
    if (beg == end)
        #pragma unroll
        for (int i = 0; i < 8; ++i) m[i] = 0.f;

    float zr[8];
    h8_to_f(__ldg((const uint4*)(g_Zh + ((size_t)25 * NN + h) * DD + c)), zr);
    const float4 bi0 = __ldg((const float4*)(bias + c));
    const float4 bi1 = __ldg((const float4*)(bias + c + 4));
    float res[8];
    res[0] = m[0] + zr[0] + bi0.x; res[1] = m[1] + zr[1] + bi0.y;
    res[2] = m[2] + zr[2] + bi0.z; res[3] = m[3] + zr[3] + bi0.w;
    res[4] = m[4] + zr[4] + bi1.x; res[5] = m[5] + zr[5] + bi1.y;
    res[6] = m[6] + zr[6] + bi1.z; res[7] = m[7] + zr[7] + bi1.w;

    const size_t o = (size_t)h * DD + c;
    if (layer == 0) {
        uint4 w;
        __half2 p0 = __floats2half2_rn(fmaxf(res[0], 0.f), fmaxf(res[1], 0.f));
        __half2 p1 = __floats2half2_rn(fmaxf(res[2], 0.f), fmaxf(res[3], 0.f));
        __half2 p2 = __floats2half2_rn(fmaxf(res[4], 0.f), fmaxf(res[5], 0.f));
        __half2 p3 = __floats2half2_rn(fmaxf(res[6], 0.f), fmaxf(res[7], 0.f));
        w.x = *(uint32_t*)&p0; w.y = *(uint32_t*)&p1;
        w.z = *(uint32_t*)&p2; w.w = *(uint32_t*)&p3;
        *(uint4*)(&g_Ah[o]) = w;
    } else {
        const float4 d0 = __ldg((const float4*)(descs + o));
        const float4 d1 = __ldg((const float4*)(descs + o + 4));
        float4 o0 = make_float4(d0.x + 0.1f * res[0], d0.y + 0.1f * res[1],
                                d0.z + 0.1f * res[2], d0.w + 0.1f * res[3]);
        float4 o1 = make_float4(d1.x + 0.1f * res[4], d1.y + 0.1f * res[5],
                                d1.z + 0.1f * res[6], d1.w + 0.1f * res[7]);
        *(float4*)(out + o)     = o0;
        *(float4*)(out + o + 4) = o1;
    }
}

// ---------------- launch ---------------------------------------------------------
extern "C" void kernel_launch(void* const* d_in, const int* in_sizes, int n_in,
                              void* d_out, int out_size) {
    const float* descs = (const float*)d_in[0];
    const float* pts   = (const float*)d_in[1];
    const float* W1    = (const float*)d_in[2];
    const float* root1 = (const float*)d_in[3];
    const float* bias1 = (const float*)d_in[4];
    const float* W2    = (const float*)d_in[5];
    const float* root2 = (const float*)d_in[6];
    const float* bias2 = (const float*)d_in[7];
    const int*   tails = (const int*)d_in[8];
    const int*   heads = (const int*)d_in[9];
    float* out = (float*)d_out;

    cudaFuncSetAttribute(gemm_fp16, cudaFuncAttributeMaxDynamicSharedMemorySize, SMEM_TOTAL);

    // zero g_cnt/g_fill via capturable async memsets
    void* cnt_ptr = nullptr;  cudaGetSymbolAddress(&cnt_ptr, g_cnt);
    void* fill_ptr = nullptr; cudaGetSymbolAddress(&fill_ptr, g_fill);
    cudaMemsetAsync(cnt_ptr, 0, NN * sizeof(int));
    cudaMemsetAsync(fill_ptr, 0, NN * sizeof(int));

    // ncu captures launch #4 -> keep gemm_fp16 there.
    cvt_a<<<4096, 256>>>(descs);                                           // 1
    cvt_w_t<<<dim3(32, 16, 52), dim3(32, 8)>>>(W1, root1, W2, root2);      // 2
    hist<<<256, 256>>>(heads);                                             // 3
    gemm_fp16<<<dim3(8, 32, 26), 256, SMEM_TOTAL>>>(0);                    // 4  <- profiled
    scan_rowptr<<<1, 1024>>>();                                            // 5
    build_edges<<<256, 256>>>(pts, tails, heads);                          // 6
    agg<<<4096, 128>>>(0, bias1, nullptr, nullptr);                        // 7
    gemm_fp16<<<dim3(8, 32, 26), 256, SMEM_TOTAL>>>(1);                    // 8
    agg<<<4096, 128>>>(1, bias2, descs, out);                              // 9
}